// round 3
// baseline (speedup 1.0000x reference)
#include <cuda_runtime.h>
#include <math.h>

// ---------------------------------------------------------------------------
// Scratch arena (floats)
// ---------------------------------------------------------------------------
#define SZ_PREQG   (2048L*1024)
#define SZ_PREQC   (2048L*512)
#define SZ_PLFW    (32768L*2048)
#define SZ_PLBW    (32768L*2048)
#define SZ_PRER    (32768L*512)
#define SZ_PREC    (32768L*512)
#define SZ_FFW     (32768L*512)
#define SZ_FBW     (32768L*512)
#define SZ_FACT    (32768L*512)
#define SZ_ATTH    (32768L*512)
#define SZ_ATT     (32768L)
#define SZ_GATE    (32768L)
#define SZ_H       (32768L)
#define SZ_RH      (32768L)
#define SZ_U       (32768L)
#define SZ_QVEC    (32768L)
#define SZ_LH      (131072L)
#define SZ_LC      (65536L)
#define SZ_MEM     (65536L)
#define SZ_AS      (32768L)
#define SZ_AE      (32768L)
#define SZ_OUTS0   (32768L)
#define SZ_OUTE0   (32768L)
#define SZ_PART    (262144L)        // AGRU partials: [8 kt][64 b][512 n]
#define SZ_RMFW    (32768L)
#define SZ_RMBW    (32768L)

#define O_PREQG  0L
#define O_PREQC  (O_PREQG + SZ_PREQG)
#define O_PLFW   (O_PREQC + SZ_PREQC)
#define O_PLBW   (O_PLFW  + SZ_PLFW)
#define O_PRER   (O_PLBW  + SZ_PLBW)
#define O_PREC   (O_PRER  + SZ_PRER)
#define O_FFW    (O_PREC  + SZ_PREC)
#define O_FBW    (O_FFW   + SZ_FFW)
#define O_FACT   (O_FBW   + SZ_FBW)
#define O_ATTH   (O_FACT  + SZ_FACT)
#define O_ATT    (O_ATTH  + SZ_ATTH)
#define O_GATE   (O_ATT   + SZ_ATT)
#define O_H      (O_GATE  + SZ_GATE)
#define O_RH     (O_H     + SZ_H)
#define O_U      (O_RH    + SZ_RH)
#define O_QVEC   (O_U     + SZ_U)
#define O_LH     (O_QVEC  + SZ_QVEC)
#define O_LC     (O_LH    + SZ_LH)
#define O_MEM    (O_LC    + SZ_LC)
#define O_AS     (O_MEM   + SZ_MEM)
#define O_AE     (O_AS    + SZ_AS)
#define O_OUTS0  (O_AE    + SZ_AE)
#define O_OUTE0  (O_OUTS0 + SZ_OUTS0)
#define O_PART   (O_OUTE0 + SZ_OUTE0)
#define O_RMFW   (O_PART  + SZ_PART)
#define O_RMBW   (O_RMFW  + SZ_RMFW)
#define SCR_TOTAL (O_RMBW + SZ_RMBW)

__device__ float g_scratch[SCR_TOTAL];
__device__ volatile unsigned g_flags[256];

__device__ __forceinline__ float sigf(float x){ return 1.0f/(1.0f+expf(-x)); }

// flag-array grid barrier: one volatile store + poll; all blocks co-resident.
__device__ __forceinline__ void flatbar(int nb, unsigned gen){
    __syncthreads();
    __threadfence();
    if (threadIdx.x == 0) g_flags[blockIdx.x] = gen;
    if (threadIdx.x < nb){
        while (g_flags[threadIdx.x] < gen) { }
    }
    __threadfence();
    __syncthreads();
}

// ---------------------------------------------------------------------------
// tiny helpers
// ---------------------------------------------------------------------------
__global__ void k_zero(float* __restrict__ p, int n){
    int i = blockIdx.x*256 + threadIdx.x;
    if (i < n) p[i] = 0.f;
}
__global__ void k_zerou(unsigned* __restrict__ p){
    p[threadIdx.x] = 0u;   // 256 threads
}
__global__ void k_copy2(float* __restrict__ d1, float* __restrict__ d2, const float* __restrict__ s){
    int i = blockIdx.x*256 + threadIdx.x;   // grid 128
    float v = s[i];
    d1[i] = v; d2[i] = v;
}
__global__ void k_rowmaps(const int* __restrict__ ids, const int* __restrict__ ilen,
                          int* __restrict__ rmfw, int* __restrict__ rmbw){
    int idx = blockIdx.x*256 + threadIdx.x;   // grid 128
    int b = idx >> 9, t = idx & 511;
    rmfw[idx] = ids[idx];
    int L = ilen[b];
    int rt = (t < L) ? (L - 1 - t) : t;
    rmbw[idx] = ids[b*512 + rt];
}
__global__ void k_combine(float* __restrict__ dst, const float* __restrict__ a, const float* __restrict__ b){
    long i = (long)blockIdx.x*256 + threadIdx.x;   // grid 16384
    float4 x = ((const float4*)a)[i];
    float4 y = ((const float4*)b)[i];
    ((float4*)dst)[i] = make_float4(x.x+y.x, x.y+y.y, x.z+y.z, x.w+y.w);
}
__global__ void k_gather_rows(float* __restrict__ dst, const float* __restrict__ emb, const int* __restrict__ idx){
    int b = blockIdx.x, tid = threadIdx.x;
    long r = idx[b];
    dst[b*512 + tid]       = emb[r*512 + tid];
    dst[b*512 + 256 + tid] = emb[r*512 + 256 + tid];
}
__global__ void k_argmax_gather(const float* __restrict__ logits, const float* __restrict__ emb, float* __restrict__ dst){
    __shared__ float sv[256];
    __shared__ int   si[256];
    int b = blockIdx.x, tid = threadIdx.x;
    float v0 = logits[b*512 + tid];
    float v1 = logits[b*512 + 256 + tid];
    float bv; int bi;
    if (v1 > v0){ bv = v1; bi = tid + 256; } else { bv = v0; bi = tid; }
    sv[tid] = bv; si[tid] = bi;
    __syncthreads();
    for (int s = 128; s > 0; s >>= 1){
        if (tid < s){
            float ov = sv[tid+s]; int oi = si[tid+s];
            if (ov > sv[tid] || (ov == sv[tid] && oi < si[tid])){ sv[tid] = ov; si[tid] = oi; }
        }
        __syncthreads();
    }
    long idx = si[0];
    dst[b*512 + tid]       = emb[idx*512 + tid];
    dst[b*512 + 256 + tid] = emb[idx*512 + 256 + tid];
}

// ---------------------------------------------------------------------------
// Big GEMM: C[M,N] = A[M,K] @ B[K,N] + bias.  128x128 tile, BK=8, 256 thr.
// ---------------------------------------------------------------------------
__global__ void __launch_bounds__(256) gemm128(
    const float* __restrict__ A, int lda, const int* __restrict__ rowmap,
    const float* __restrict__ B, int ldb,
    const float* __restrict__ bias,
    float* __restrict__ C, int ldc, int K)
{
    __shared__ float As[8][128];
    __shared__ float Bs[8][128];
    const int m0 = blockIdx.y*128, n0 = blockIdx.x*128;
    const int tid = threadIdx.x;
    const int tx = tid & 15, ty = tid >> 4;
    const int arow = tid >> 1, acol = (tid & 1)*4;
    const int brow = tid >> 5, bcol = (tid & 31)*4;
    long ar = rowmap ? (long)rowmap[m0 + arow] : (long)(m0 + arow);
    const float* Ap = A + ar*lda + acol;
    const float* Bp = B + (long)brow*ldb + n0 + bcol;
    float acc[8][8] = {};
    for (int k0 = 0; k0 < K; k0 += 8){
        float4 a4 = *(const float4*)(Ap + k0);
        As[acol+0][arow] = a4.x; As[acol+1][arow] = a4.y;
        As[acol+2][arow] = a4.z; As[acol+3][arow] = a4.w;
        *(float4*)&Bs[brow][bcol] = *(const float4*)(Bp + (long)k0*ldb);
        __syncthreads();
        #pragma unroll
        for (int kk = 0; kk < 8; kk++){
            float ra[8], rb[8];
            *(float4*)(ra)   = *(const float4*)&As[kk][ty*8];
            *(float4*)(ra+4) = *(const float4*)&As[kk][ty*8+4];
            *(float4*)(rb)   = *(const float4*)&Bs[kk][tx*8];
            *(float4*)(rb+4) = *(const float4*)&Bs[kk][tx*8+4];
            #pragma unroll
            for (int i = 0; i < 8; i++)
                #pragma unroll
                for (int j = 0; j < 8; j++)
                    acc[i][j] = fmaf(ra[i], rb[j], acc[i][j]);
        }
        __syncthreads();
    }
    #pragma unroll
    for (int i = 0; i < 8; i++){
        long m = m0 + ty*8 + i;
        #pragma unroll
        for (int j = 0; j < 8; j++){
            int n = n0 + tx*8 + j;
            C[m*ldc + n] = acc[i][j] + bias[n];
        }
    }
}

// ---------------------------------------------------------------------------
// Attention feature GEMM with on-the-fly 7H features, tanh+bias epilogue.
// ---------------------------------------------------------------------------
__global__ void __launch_bounds__(256) gemm_feats(
    const float* __restrict__ W1, const float* __restrict__ b1,
    const float* __restrict__ fact, const float* __restrict__ qvec,
    const float* __restrict__ mem, float* __restrict__ atth)
{
    __shared__ float As[8][128];
    __shared__ float Bs[8][128];
    const int m0 = blockIdx.y*128, n0 = blockIdx.x*128;
    const int tid = threadIdx.x;
    const int tx = tid & 15, ty = tid >> 4;
    const int arow = tid >> 1, acol = (tid & 1)*4;
    const int brow = tid >> 5, bcol = (tid & 31)*4;
    const int m = m0 + arow, b = m >> 9;
    const float4* fp = (const float4*)(fact + (long)m*512);
    const float4* qp = (const float4*)(qvec + (long)b*512);
    const float4* mp = (const float4*)(mem  + (long)b*512);
    const float* Bp = W1 + (long)brow*512 + n0 + bcol;
    float acc[8][8] = {};
    for (int k0 = 0; k0 < 3584; k0 += 8){
        int k = k0 + acol, seg = k >> 9, ki = (k & 511) >> 2;
        float4 v;
        if (seg == 0)      v = fp[ki];
        else if (seg == 1) v = mp[ki];
        else if (seg == 2) v = qp[ki];
        else if (seg == 3){ float4 f = fp[ki], q = qp[ki];
            v = make_float4(f.x*q.x, f.y*q.y, f.z*q.z, f.w*q.w); }
        else if (seg == 4){ float4 f = fp[ki], q = mp[ki];
            v = make_float4(f.x*q.x, f.y*q.y, f.z*q.z, f.w*q.w); }
        else if (seg == 5){ float4 f = fp[ki], q = qp[ki];
            v = make_float4(fabsf(f.x-q.x), fabsf(f.y-q.y), fabsf(f.z-q.z), fabsf(f.w-q.w)); }
        else              { float4 f = fp[ki], q = mp[ki];
            v = make_float4(fabsf(f.x-q.x), fabsf(f.y-q.y), fabsf(f.z-q.z), fabsf(f.w-q.w)); }
        As[acol+0][arow] = v.x; As[acol+1][arow] = v.y;
        As[acol+2][arow] = v.z; As[acol+3][arow] = v.w;
        *(float4*)&Bs[brow][bcol] = *(const float4*)(Bp + (long)k0*512);
        __syncthreads();
        #pragma unroll
        for (int kk = 0; kk < 8; kk++){
            float ra[8], rb[8];
            *(float4*)(ra)   = *(const float4*)&As[kk][ty*8];
            *(float4*)(ra+4) = *(const float4*)&As[kk][ty*8+4];
            *(float4*)(rb)   = *(const float4*)&Bs[kk][tx*8];
            *(float4*)(rb+4) = *(const float4*)&Bs[kk][tx*8+4];
            #pragma unroll
            for (int i = 0; i < 8; i++)
                #pragma unroll
                for (int j = 0; j < 8; j++)
                    acc[i][j] = fmaf(ra[i], rb[j], acc[i][j]);
        }
        __syncthreads();
    }
    #pragma unroll
    for (int i = 0; i < 8; i++){
        long mm = m0 + ty*8 + i;
        #pragma unroll
        for (int j = 0; j < 8; j++){
            int n = n0 + tx*8 + j;
            atth[mm*512 + n] = tanhf(acc[i][j] + b1[n]);
        }
    }
}

__global__ void k_att2(const float* __restrict__ atth, const float* __restrict__ W2,
                       const float* __restrict__ b2, float* __restrict__ att){
    int m = blockIdx.x*8 + (threadIdx.x >> 5);
    int lane = threadIdx.x & 31;
    const float* row = atth + (long)m*512;
    float s = 0.f;
    #pragma unroll
    for (int i = 0; i < 16; i++) s = fmaf(row[lane + i*32], W2[lane + i*32], s);
    #pragma unroll
    for (int o = 16; o > 0; o >>= 1) s += __shfl_xor_sync(0xffffffffu, s, o);
    if (lane == 0) att[m] = s + b2[0];
}

__global__ void k_softmax(const float* __restrict__ att, float* __restrict__ gate){
    __shared__ float red[256];
    int b = blockIdx.x, tid = threadIdx.x;
    float v0 = att[b*512 + tid], v1 = att[b*512 + 256 + tid];
    red[tid] = fmaxf(v0, v1);
    __syncthreads();
    for (int s = 128; s > 0; s >>= 1){ if (tid < s) red[tid] = fmaxf(red[tid], red[tid+s]); __syncthreads(); }
    float mx = red[0];
    __syncthreads();
    float e0 = expf(v0 - mx), e1 = expf(v1 - mx);
    red[tid] = e0 + e1;
    __syncthreads();
    for (int s = 128; s > 0; s >>= 1){ if (tid < s) red[tid] += red[tid+s]; __syncthreads(); }
    float inv = 1.f/red[0];
    gate[b*512 + tid]       = e0*inv;
    gate[b*512 + 256 + tid] = e1*inv;
}

// ---------------------------------------------------------------------------
// Persistent question GRU: 32 blocks, 32 steps, 2 flat barriers/step.
// ---------------------------------------------------------------------------
__global__ void __launch_bounds__(256) pk_gru(
    const float* __restrict__ Wg,   // qWg + 512*1024 (h rows), ldb 1024
    const float* __restrict__ Wc,   // qWc + 512*512  (rh rows), ldb 512
    const float* __restrict__ preg, const float* __restrict__ prec,
    const int* __restrict__ qlen,
    float* __restrict__ h, float* __restrict__ rh, float* __restrict__ u)
{
    __shared__ float As[16][64];
    __shared__ float Bs[16][32];
    const int tid = threadIdx.x, bx = blockIdx.x;
    const int tx = tid & 31, ty = tid >> 5;
    const int arow = tid >> 2, acol = (tid & 3)*4;
    unsigned gen = 0;
    for (int t = 0; t < 32; t++){
        {   // gate phase: Z[64,1024] = h @ Wg_h, cols bx*32..
            const int n0 = bx*32;
            float acc[8] = {};
            for (int k0 = 0; k0 < 512; k0 += 16){
                float4 a4 = __ldcg((const float4*)(h + arow*512 + k0 + acol));
                As[acol+0][arow]=a4.x; As[acol+1][arow]=a4.y;
                As[acol+2][arow]=a4.z; As[acol+3][arow]=a4.w;
                if (tid < 128){
                    int kk = tid >> 3, c4 = (tid & 7)*4;
                    *(float4*)&Bs[kk][c4] = *(const float4*)(Wg + (long)(k0+kk)*1024 + n0 + c4);
                }
                __syncthreads();
                #pragma unroll
                for (int kk = 0; kk < 16; kk++){
                    float ra[8];
                    *(float4*)(ra)   = *(const float4*)&As[kk][ty*8];
                    *(float4*)(ra+4) = *(const float4*)&As[kk][ty*8+4];
                    float rb = Bs[kk][tx];
                    #pragma unroll
                    for (int i = 0; i < 8; i++) acc[i] = fmaf(ra[i], rb, acc[i]);
                }
                __syncthreads();
            }
            int n = n0 + tx;
            #pragma unroll
            for (int i = 0; i < 8; i++){
                int b = ty*8 + i;
                float z = acc[i] + preg[((long)b*32 + t)*1024 + n];
                float s = sigf(z);
                if (n < 512) __stcg(rh + b*512 + n, s * __ldcg(h + b*512 + n));
                else         __stcg(u + b*512 + (n - 512), s);
            }
        }
        flatbar(32, ++gen);
        if (bx < 16){   // candidate phase: Z[64,512] = rh @ Wc_h
            const int n0 = bx*32;
            float acc[8] = {};
            for (int k0 = 0; k0 < 512; k0 += 16){
                float4 a4 = __ldcg((const float4*)(rh + arow*512 + k0 + acol));
                As[acol+0][arow]=a4.x; As[acol+1][arow]=a4.y;
                As[acol+2][arow]=a4.z; As[acol+3][arow]=a4.w;
                if (tid < 128){
                    int kk = tid >> 3, c4 = (tid & 7)*4;
                    *(float4*)&Bs[kk][c4] = *(const float4*)(Wc + (long)(k0+kk)*512 + n0 + c4);
                }
                __syncthreads();
                #pragma unroll
                for (int kk = 0; kk < 16; kk++){
                    float ra[8];
                    *(float4*)(ra)   = *(const float4*)&As[kk][ty*8];
                    *(float4*)(ra+4) = *(const float4*)&As[kk][ty*8+4];
                    float rb = Bs[kk][tx];
                    #pragma unroll
                    for (int i = 0; i < 8; i++) acc[i] = fmaf(ra[i], rb, acc[i]);
                }
                __syncthreads();
            }
            int n = n0 + tx;
            #pragma unroll
            for (int i = 0; i < 8; i++){
                int b = ty*8 + i;
                float c = tanhf(acc[i] + prec[((long)b*32 + t)*512 + n]);
                float uu = __ldcg(u + b*512 + n);
                float ho = __ldcg(h + b*512 + n);
                float hn = (t < qlen[b]) ? (uu*ho + (1.f - uu)*c) : ho;
                __stcg(h + b*512 + n, hn);
            }
        }
        flatbar(32, ++gen);
    }
}

// ---------------------------------------------------------------------------
// Persistent bi-LSTM: 128 blocks (2 dirs x 64 hidden-chunks of 8), 512 steps,
// smem Z exchange for cross-gate epilogue, ping-pong h, 1 barrier/step.
// ---------------------------------------------------------------------------
__global__ void __launch_bounds__(256) pk_lstm(
    const float* __restrict__ Wfwh, const float* __restrict__ Wbwh, // + 512*2048
    const float* __restrict__ prefw, const float* __restrict__ prebw,
    const int* __restrict__ ilen,
    float* __restrict__ lh, float* __restrict__ lc,
    float* __restrict__ ffw, float* __restrict__ fbw)
{
    __shared__ float As[16][64];
    __shared__ float Bs[16][32];
    __shared__ float zs[64][32];
    const int tid = threadIdx.x;
    const int dir = blockIdx.x >> 6;
    const int hc8 = (blockIdx.x & 63)*8;
    const float* Wh  = dir ? Wbwh : Wfwh;
    const float* pre = dir ? prebw : prefw;
    float* cbuf = lc + dir*32768;
    float* outp = dir ? fbw : ffw;
    const int tx = tid & 31, ty = tid >> 5;
    const int arow = tid >> 2, acol = (tid & 3)*4;
    unsigned gen = 0;
    for (int t = 0; t < 512; t++){
        const int par = t & 1;
        const float* hin = lh + par*65536 + dir*32768;
        float* hout = lh + (par^1)*65536 + dir*32768;
        float acc[8] = {};
        for (int k0 = 0; k0 < 512; k0 += 16){
            float4 a4 = __ldcg((const float4*)(hin + arow*512 + k0 + acol));
            As[acol+0][arow]=a4.x; As[acol+1][arow]=a4.y;
            As[acol+2][arow]=a4.z; As[acol+3][arow]=a4.w;
            if (tid < 128){
                int kk = tid >> 3, rem = tid & 7;
                int gg = rem >> 1, h4 = (rem & 1)*4;
                *(float4*)&Bs[kk][gg*8 + h4] =
                    *(const float4*)(Wh + (long)(k0+kk)*2048 + gg*512 + hc8 + h4);
            }
            __syncthreads();
            #pragma unroll
            for (int kk = 0; kk < 16; kk++){
                float ra[8];
                *(float4*)(ra)   = *(const float4*)&As[kk][ty*8];
                *(float4*)(ra+4) = *(const float4*)&As[kk][ty*8+4];
                float rb = Bs[kk][tx];
                #pragma unroll
                for (int i = 0; i < 8; i++) acc[i] = fmaf(ra[i], rb, acc[i]);
            }
            __syncthreads();
        }
        #pragma unroll
        for (int i = 0; i < 8; i++) zs[ty*8 + i][tx] = acc[i];
        __syncthreads();
        #pragma unroll
        for (int e = 0; e < 2; e++){
            int uix = tid*2 + e;
            int b = uix >> 3, j = uix & 7, hc = hc8 + j;
            long prow = ((long)b*512 + t)*2048;
            float zi = zs[b][j]       + pre[prow + hc];
            float zj = zs[b][8 + j]   + pre[prow + 512 + hc];
            float zf = zs[b][16 + j]  + pre[prow + 1024 + hc];
            float zo = zs[b][24 + j]  + pre[prow + 1536 + hc];
            float c_old = cbuf[b*512 + hc];
            float cn = sigf(zf + 1.f)*c_old + sigf(zi)*tanhf(zj);
            float hn = sigf(zo)*tanhf(cn);
            int L = ilen[b];
            bool m = t < L;
            float h_old = __ldcg(hin + b*512 + hc);
            __stcg(hout + b*512 + hc, m ? hn : h_old);
            cbuf[b*512 + hc] = m ? cn : c_old;
            int wt = dir ? (m ? (L - 1 - t) : t) : t;
            __stcg(outp + ((long)b*512 + wt)*512 + hc, m ? hn : 0.f);
        }
        flatbar(128, ++gen);
    }
}

// ---------------------------------------------------------------------------
// Persistent AGRU: 64 blocks = 8 n-tiles x 8 k-tiles; per step:
// C1(partials h@Ur) B R1(reduce->rh) B C2(partials rh@Uc) B R2(reduce->h) B
// ---------------------------------------------------------------------------
__device__ __forceinline__ void agru_partial(
    const float* __restrict__ A, const float* __restrict__ W,
    float* __restrict__ P, int nt, int kt,
    float (&As)[64][64], float (&Bs)[64][64])
{
    const int tid = threadIdx.x;
    const int tx = tid & 31, ty = tid >> 5;
    const int kbase = kt*64, nbase = nt*64;
    {
        int b = tid >> 2, k4 = (tid & 3)*4;
        #pragma unroll
        for (int c = 0; c < 4; c++){
            float4 a4 = __ldcg((const float4*)(A + b*512 + kbase + k4 + c*16));
            As[k4 + c*16 + 0][b] = a4.x;
            As[k4 + c*16 + 1][b] = a4.y;
            As[k4 + c*16 + 2][b] = a4.z;
            As[k4 + c*16 + 3][b] = a4.w;
        }
        int r0 = tid >> 4, c4 = (tid & 15)*4;
        #pragma unroll
        for (int c = 0; c < 4; c++)
            *(float4*)&Bs[r0 + c*16][c4] =
                *(const float4*)(W + (long)(kbase + r0 + c*16)*512 + nbase + c4);
    }
    __syncthreads();
    float acc[8][2] = {};
    #pragma unroll 8
    for (int kk = 0; kk < 64; kk++){
        float ra[8];
        *(float4*)(ra)   = *(const float4*)&As[kk][ty*8];
        *(float4*)(ra+4) = *(const float4*)&As[kk][ty*8+4];
        float2 rb = *(const float2*)&Bs[kk][tx*2];
        #pragma unroll
        for (int i = 0; i < 8; i++){
            acc[i][0] = fmaf(ra[i], rb.x, acc[i][0]);
            acc[i][1] = fmaf(ra[i], rb.y, acc[i][1]);
        }
    }
    #pragma unroll
    for (int i = 0; i < 8; i++){
        int b = ty*8 + i;
        __stcg((float2*)(P + (long)kt*32768 + b*512 + nbase + tx*2),
               make_float2(acc[i][0], acc[i][1]));
    }
}

template<int PHASE>   // 0: r-phase (-> rh), 1: candidate phase (-> h)
__device__ __forceinline__ void agru_reduce(
    const float* __restrict__ P, const float* __restrict__ pre,
    const float* __restrict__ gate, const int* __restrict__ ilen,
    float* __restrict__ h, float* __restrict__ rh, int t)
{
    const int colbase = blockIdx.x*8;
    #pragma unroll
    for (int e = 0; e < 2; e++){
        int uix = threadIdx.x*2 + e;
        int b = uix >> 3, n = colbase + (uix & 7);
        float z = pre[((long)b*512 + t)*512 + n];
        #pragma unroll
        for (int kt = 0; kt < 8; kt++)
            z += __ldcg(P + (long)kt*32768 + b*512 + n);
        if (PHASE == 0){
            float r = sigf(z);
            __stcg(rh + b*512 + n, r * __ldcg(h + b*512 + n));
        } else {
            float hh = tanhf(z);
            float g = gate[b*512 + t];
            float ho = __ldcg(h + b*512 + n);
            float hn = (t < ilen[b]) ? (g*hh + (1.f - g)*ho) : ho;
            __stcg(h + b*512 + n, hn);
        }
    }
}

__global__ void __launch_bounds__(256) pk_agru(
    const float* __restrict__ Ur, const float* __restrict__ Uc,
    const float* __restrict__ prer, const float* __restrict__ prec,
    const float* __restrict__ gate, const int* __restrict__ ilen,
    float* __restrict__ h, float* __restrict__ rh, float* __restrict__ P)
{
    __shared__ float As[64][64];
    __shared__ float Bs[64][64];
    const int nt = blockIdx.x & 7, kt = blockIdx.x >> 3;
    unsigned gen = 0;
    for (int t = 0; t < 512; t++){
        agru_partial(h, Ur, P, nt, kt, As, Bs);
        flatbar(64, ++gen);
        agru_reduce<0>(P, prer, gate, ilen, h, rh, t);
        flatbar(64, ++gen);
        agru_partial(rh, Uc, P, nt, kt, As, Bs);
        flatbar(64, ++gen);
        agru_reduce<1>(P, prec, gate, ilen, h, rh, t);
        flatbar(64, ++gen);
    }
}

// ---------------------------------------------------------------------------
// Concat-A GEMM: C[64,512] = act([p0|p1|p2|p3|p4] @ W + bias), segs 512 each.
// ---------------------------------------------------------------------------
template<int ACT>
__global__ void __launch_bounds__(256) k_catgemm(
    const float* __restrict__ p0, const float* __restrict__ p1,
    const float* __restrict__ p2, const float* __restrict__ p3,
    const float* __restrict__ p4,
    const float* __restrict__ W, const float* __restrict__ bias,
    float* __restrict__ C, int K)
{
    const float* segs[5] = {p0, p1, p2, p3, p4};
    __shared__ float As[16][64];
    __shared__ float Bs[16][64];
    const int n0 = blockIdx.x*64;
    const int tid = threadIdx.x;
    const int tx = tid & 31, ty = tid >> 5;
    const int arow = tid >> 2, acol = (tid & 3)*4;
    const int brow = tid >> 4, bcol = (tid & 15)*4;
    float acc[8][2] = {};
    for (int k0 = 0; k0 < K; k0 += 16){
        int k = k0 + acol;
        const float* sp = segs[k >> 9];
        float4 a4 = *(const float4*)(sp + arow*512 + (k & 511));
        As[acol+0][arow] = a4.x; As[acol+1][arow] = a4.y;
        As[acol+2][arow] = a4.z; As[acol+3][arow] = a4.w;
        *(float4*)&Bs[brow][bcol] = *(const float4*)(W + (long)(k0+brow)*512 + n0 + bcol);
        __syncthreads();
        #pragma unroll
        for (int kk = 0; kk < 16; kk++){
            float ra[8];
            *(float4*)(ra)   = *(const float4*)&As[kk][ty*8];
            *(float4*)(ra+4) = *(const float4*)&As[kk][ty*8+4];
            float2 rb = *(const float2*)&Bs[kk][tx*2];
            #pragma unroll
            for (int i = 0; i < 8; i++){
                acc[i][0] = fmaf(ra[i], rb.x, acc[i][0]);
                acc[i][1] = fmaf(ra[i], rb.y, acc[i][1]);
            }
        }
        __syncthreads();
    }
    #pragma unroll
    for (int i = 0; i < 8; i++){
        int b = ty*8 + i;
        #pragma unroll
        for (int j = 0; j < 2; j++){
            int n = n0 + tx*2 + j;
            float v = acc[i][j] + bias[n];
            if (ACT == 1) v = fmaxf(v, 0.f);
            C[b*512 + n] = v;
        }
    }
}

// ---------------------------------------------------------------------------
// host launcher
// ---------------------------------------------------------------------------
extern "C" void kernel_launch(void* const* d_in, const int* in_sizes, int n_in,
                              void* d_out, int out_size)
{
    (void)in_sizes; (void)n_in; (void)out_size;
    const int*   question  = (const int*)  d_in[0];
    const int*   input_ids = (const int*)  d_in[1];
    const int*   qlen      = (const int*)  d_in[2];
    const int*   ilen      = (const int*)  d_in[3];
    const int*   start     = (const int*)  d_in[4];
    const float* emb       = (const float*)d_in[5];
    const float* qWg       = (const float*)d_in[6];
    const float* qbg       = (const float*)d_in[7];
    const float* qWc       = (const float*)d_in[8];
    const float* qbc       = (const float*)d_in[9];
    const float* lfW       = (const float*)d_in[10];
    const float* lfb       = (const float*)d_in[11];
    const float* lbW       = (const float*)d_in[12];
    const float* lbb       = (const float*)d_in[13];
    const float* aW1       = (const float*)d_in[14];
    const float* ab1       = (const float*)d_in[15];
    const float* aW2       = (const float*)d_in[16];
    const float* ab2       = (const float*)d_in[17];
    const float* Wr        = (const float*)d_in[18];
    const float* Ur        = (const float*)d_in[19];
    const float* br        = (const float*)d_in[20];
    const float* Wc        = (const float*)d_in[21];
    const float* Uc        = (const float*)d_in[22];
    const float* bc        = (const float*)d_in[23];
    const float* hopW      = (const float*)d_in[24];
    const float* hopB      = (const float*)d_in[25];
    const float* osW       = (const float*)d_in[26];
    const float* osB       = (const float*)d_in[27];
    const float* oeW       = (const float*)d_in[28];
    const float* oeB       = (const float*)d_in[29];
    float* out = (float*)d_out;

    float* S = nullptr;
    cudaGetSymbolAddress((void**)&S, g_scratch);
    unsigned* flags = nullptr;
    cudaGetSymbolAddress((void**)&flags, (const void*)g_flags);

    float* preqg = S + O_PREQG;
    float* preqc = S + O_PREQC;
    float* plfw  = S + O_PLFW;
    float* plbw  = S + O_PLBW;
    float* prer  = S + O_PRER;
    float* prec  = S + O_PREC;
    float* ffw   = S + O_FFW;
    float* fbw   = S + O_FBW;
    float* fact  = S + O_FACT;
    float* atth  = S + O_ATTH;
    float* att   = S + O_ATT;
    float* gate  = S + O_GATE;
    float* h     = S + O_H;
    float* rh    = S + O_RH;
    float* u     = S + O_U;
    float* qvec  = S + O_QVEC;
    float* lh    = S + O_LH;
    float* lc    = S + O_LC;
    float* mem   = S + O_MEM;
    float* as_   = S + O_AS;
    float* ae_   = S + O_AE;
    float* outs0 = S + O_OUTS0;
    float* oute0 = S + O_OUTE0;
    float* part  = S + O_PART;
    int*   rmfw  = (int*)(S + O_RMFW);
    int*   rmbw  = (int*)(S + O_RMBW);

    // init
    k_zero<<<128, 256>>>(h, 32768);
    k_zero<<<512, 256>>>(lh, 131072);
    k_zero<<<256, 256>>>(lc, 65536);
    k_zero<<<128, 256>>>(as_, 32768);
    k_zero<<<128, 256>>>(ae_, 32768);
    k_rowmaps<<<128, 256>>>(input_ids, ilen, rmfw, rmbw);

    // input-side precomputes (biases folded)
    gemm128<<<dim3(8, 16),  256>>>(emb, 512, question, qWg, 1024, qbg, preqg, 1024, 512);
    gemm128<<<dim3(4, 16),  256>>>(emb, 512, question, qWc,  512, qbc, preqc,  512, 512);
    gemm128<<<dim3(16,256), 256>>>(emb, 512, rmfw,     lfW, 2048, lfb, plfw,  2048, 512);
    gemm128<<<dim3(16,256), 256>>>(emb, 512, rmbw,     lbW, 2048, lbb, plbw,  2048, 512);

    // question GRU (persistent)
    k_zerou<<<1, 256>>>(flags);
    pk_gru<<<32, 256>>>(qWg + 512L*1024, qWc + 512L*512, preqg, preqc, qlen, h, rh, u);
    k_copy2<<<128, 256>>>(qvec, mem, h);

    // bi-LSTM (persistent)
    k_zerou<<<1, 256>>>(flags);
    pk_lstm<<<128, 256>>>(lfW + 512L*2048, lbW + 512L*2048, plfw, plbw, ilen, lh, lc, ffw, fbw);
    k_combine<<<16384, 256>>>(fact, ffw, fbw);

    // AGRU input-side precompute (hop-invariant)
    gemm128<<<dim3(4,256), 256>>>(fact, 512, nullptr, Wr, 512, br, prer, 512, 512);
    gemm128<<<dim3(4,256), 256>>>(fact, 512, nullptr, Wc, 512, bc, prec, 512, 512);

    // hops
    int cur = 0;
    for (int hop = 0; hop < 3; hop++){
        gemm_feats<<<dim3(4,256), 256>>>(aW1, ab1, fact, qvec, mem + cur*32768, atth);
        k_att2<<<4096, 256>>>(atth, aW2, ab2, att);
        k_softmax<<<64, 256>>>(att, gate);

        k_zero<<<128, 256>>>(h, 32768);
        k_zerou<<<1, 256>>>(flags);
        pk_agru<<<64, 256>>>(Ur, Uc, prer, prec, gate, ilen, h, rh, part);

        if (hop == 2){
            k_gather_rows<<<64, 256>>>(as_, emb, start);
            k_gather_rows<<<64, 256>>>(ae_, emb, start);
        }
        int nxt = cur ^ 1;
        k_catgemm<1><<<8, 256>>>(mem + cur*32768, h, qvec, as_, ae_,
                                 hopW + (long)hop*2560*512, hopB + hop*512,
                                 mem + nxt*32768, 2560);
        if (hop == 0){
            k_catgemm<0><<<8, 256>>>(mem + nxt*32768, qvec, qvec, qvec, qvec, osW, osB, outs0, 1024);
            k_catgemm<0><<<8, 256>>>(mem + nxt*32768, qvec, qvec, qvec, qvec, oeW, oeB, oute0, 1024);
            k_argmax_gather<<<64, 256>>>(outs0, emb, ae_);   // a_e = emb[argmax(output_s)]
            k_argmax_gather<<<64, 256>>>(oute0, emb, as_);   // a_s = emb[argmax(output_e)]
        }
        if (hop == 2){
            k_catgemm<0><<<8, 256>>>(mem + nxt*32768, qvec, qvec, qvec, qvec, osW, osB, out, 1024);
            k_catgemm<0><<<8, 256>>>(mem + nxt*32768, qvec, qvec, qvec, qvec, oeW, oeB, out + 32768, 1024);
        }
        cur = nxt;
    }
}

// round 4
// speedup vs baseline: 1.0119x; 1.0119x over previous
#include <cuda_runtime.h>
#include <math.h>

// ---------------------------------------------------------------------------
// Scratch arena (floats)
// ---------------------------------------------------------------------------
#define SZ_PREQG   (2048L*1024)
#define SZ_PREQC   (2048L*512)
#define SZ_PLFW    (32768L*2048)
#define SZ_PLBW    (32768L*2048)
#define SZ_PRER    (32768L*512)
#define SZ_PREC    (32768L*512)
#define SZ_FFW     (32768L*512)
#define SZ_FBW     (32768L*512)
#define SZ_FACT    (32768L*512)
#define SZ_ATTH    (32768L*512)
#define SZ_ATT     (32768L)
#define SZ_GATE    (32768L)
#define SZ_H       (32768L)
#define SZ_RH      (32768L)
#define SZ_U       (32768L)
#define SZ_QVEC    (32768L)
#define SZ_LH      (131072L)
#define SZ_LC      (65536L)
#define SZ_MEM     (65536L)
#define SZ_AS      (32768L)
#define SZ_AE      (32768L)
#define SZ_OUTS0   (32768L)
#define SZ_OUTE0   (32768L)
#define SZ_RMFW    (32768L)
#define SZ_RMBW    (32768L)

#define O_PREQG  0L
#define O_PREQC  (O_PREQG + SZ_PREQG)
#define O_PLFW   (O_PREQC + SZ_PREQC)
#define O_PLBW   (O_PLFW  + SZ_PLFW)
#define O_PRER   (O_PLBW  + SZ_PLBW)
#define O_PREC   (O_PRER  + SZ_PRER)
#define O_FFW    (O_PREC  + SZ_PREC)
#define O_FBW    (O_FFW   + SZ_FFW)
#define O_FACT   (O_FBW   + SZ_FBW)
#define O_ATTH   (O_FACT  + SZ_FACT)
#define O_ATT    (O_ATTH  + SZ_ATTH)
#define O_GATE   (O_ATT   + SZ_ATT)
#define O_H      (O_GATE  + SZ_GATE)
#define O_RH     (O_H     + SZ_H)
#define O_U      (O_RH    + SZ_RH)
#define O_QVEC   (O_U     + SZ_U)
#define O_LH     (O_QVEC  + SZ_QVEC)
#define O_LC     (O_LH    + SZ_LH)
#define O_MEM    (O_LC    + SZ_LC)
#define O_AS     (O_MEM   + SZ_MEM)
#define O_AE     (O_AS    + SZ_AS)
#define O_OUTS0  (O_AE    + SZ_AE)
#define O_OUTE0  (O_OUTS0 + SZ_OUTS0)
#define O_RMFW   (O_OUTE0 + SZ_OUTE0)
#define O_RMBW   (O_RMFW  + SZ_RMFW)
#define SCR_TOTAL (O_RMBW + SZ_RMBW)

__device__ float g_scratch[SCR_TOTAL];
__device__ unsigned g_flags[256];

__device__ __forceinline__ float sigf(float x){ return 1.0f/(1.0f+expf(-x)); }

// packed fp32x2 FMA (Blackwell double-rate fp32; exact fp32 per-half)
__device__ __forceinline__ unsigned long long fma2(unsigned long long a,
                                                   unsigned long long b,
                                                   unsigned long long c){
    unsigned long long d;
    asm("fma.rn.f32x2 %0, %1, %2, %3;" : "=l"(d) : "l"(a), "l"(b), "l"(c));
    return d;
}
__device__ __forceinline__ float2 ull2f2(unsigned long long u){
    float2 f;
    asm("mov.b64 {%0, %1}, %2;" : "=f"(f.x), "=f"(f.y) : "l"(u));
    return f;
}

// release/acquire grid barrier (no MEMBAR.GPU drain); all blocks co-resident.
__device__ __forceinline__ void flatbar(int nb, unsigned gen){
    __syncthreads();
    if (threadIdx.x == 0){
        asm volatile("st.release.gpu.global.u32 [%0], %1;"
                     :: "l"(g_flags + blockIdx.x), "r"(gen) : "memory");
    }
    if (threadIdx.x < nb){
        unsigned v;
        do {
            asm volatile("ld.acquire.gpu.global.u32 %0, [%1];"
                         : "=r"(v) : "l"(g_flags + threadIdx.x) : "memory");
        } while (v < gen);
    }
    __syncthreads();
}

// ---------------------------------------------------------------------------
// tiny helpers
// ---------------------------------------------------------------------------
__global__ void k_init(float* __restrict__ S){
    long i = (long)blockIdx.x*256 + threadIdx.x;   // grid 512 -> 131072
    if (i < 32768){ S[O_H+i]=0.f; S[O_AS+i]=0.f; S[O_AE+i]=0.f; }
    if (i < 65536) S[O_LC+i]=0.f;
    S[O_LH+i]=0.f;
}
__global__ void k_zero(float* __restrict__ p, int n){
    int i = blockIdx.x*256 + threadIdx.x;
    if (i < n) p[i] = 0.f;
}
__global__ void k_zerou(unsigned* __restrict__ p){
    p[threadIdx.x] = 0u;   // 256 threads
}
__global__ void k_copy2(float* __restrict__ d1, float* __restrict__ d2, const float* __restrict__ s){
    int i = blockIdx.x*256 + threadIdx.x;   // grid 128
    float v = s[i];
    d1[i] = v; d2[i] = v;
}
__global__ void k_rowmaps(const int* __restrict__ ids, const int* __restrict__ ilen,
                          int* __restrict__ rmfw, int* __restrict__ rmbw){
    int idx = blockIdx.x*256 + threadIdx.x;   // grid 128
    int b = idx >> 9, t = idx & 511;
    rmfw[idx] = ids[idx];
    int L = ilen[b];
    int rt = (t < L) ? (L - 1 - t) : t;
    rmbw[idx] = ids[b*512 + rt];
}
__global__ void k_combine(float* __restrict__ dst, const float* __restrict__ a, const float* __restrict__ b){
    long i = (long)blockIdx.x*256 + threadIdx.x;   // grid 16384
    float4 x = ((const float4*)a)[i];
    float4 y = ((const float4*)b)[i];
    ((float4*)dst)[i] = make_float4(x.x+y.x, x.y+y.y, x.z+y.z, x.w+y.w);
}
__global__ void k_gather_rows(float* __restrict__ dst, const float* __restrict__ emb, const int* __restrict__ idx){
    int b = blockIdx.x, tid = threadIdx.x;
    long r = idx[b];
    dst[b*512 + tid]       = emb[r*512 + tid];
    dst[b*512 + 256 + tid] = emb[r*512 + 256 + tid];
}
__global__ void k_argmax_gather(const float* __restrict__ logits, const float* __restrict__ emb, float* __restrict__ dst){
    __shared__ float sv[256];
    __shared__ int   si[256];
    int b = blockIdx.x, tid = threadIdx.x;
    float v0 = logits[b*512 + tid];
    float v1 = logits[b*512 + 256 + tid];
    float bv; int bi;
    if (v1 > v0){ bv = v1; bi = tid + 256; } else { bv = v0; bi = tid; }
    sv[tid] = bv; si[tid] = bi;
    __syncthreads();
    for (int s = 128; s > 0; s >>= 1){
        if (tid < s){
            float ov = sv[tid+s]; int oi = si[tid+s];
            if (ov > sv[tid] || (ov == sv[tid] && oi < si[tid])){ sv[tid] = ov; si[tid] = oi; }
        }
        __syncthreads();
    }
    long idx = si[0];
    dst[b*512 + tid]       = emb[idx*512 + tid];
    dst[b*512 + 256 + tid] = emb[idx*512 + 256 + tid];
}

// ---------------------------------------------------------------------------
// Big GEMM (f32x2): C[M,N] = A[M,K] @ B[K,N] + bias. 128x128 tile, BK=8.
// A staged into smem as duplicated (a,a) pairs -> pure FFMA2 inner loop.
// ---------------------------------------------------------------------------
__global__ void __launch_bounds__(256) gemm128(
    const float* __restrict__ A, int lda, const int* __restrict__ rowmap,
    const float* __restrict__ B, int ldb,
    const float* __restrict__ bias,
    float* __restrict__ C, int ldc, int K)
{
    __shared__ float As2[8][260];   // dup pairs: As2[kk][2*row{,+1}]; stride 260 keeps 16B align
    __shared__ float Bs[8][128];
    const int m0 = blockIdx.y*128, n0 = blockIdx.x*128;
    const int tid = threadIdx.x;
    const int tx = tid & 15, ty = tid >> 4;
    const int arow = tid >> 1, acol = (tid & 1)*4;
    const int brow = tid >> 5, bcol = (tid & 31)*4;
    long ar = rowmap ? (long)rowmap[m0 + arow] : (long)(m0 + arow);
    const float* Ap = A + ar*lda + acol;
    const float* Bp = B + (long)brow*ldb + n0 + bcol;
    unsigned long long acc[8][4];
    #pragma unroll
    for (int i = 0; i < 8; i++)
        #pragma unroll
        for (int j = 0; j < 4; j++) acc[i][j] = 0ull;

    for (int k0 = 0; k0 < K; k0 += 8){
        float4 a4 = *(const float4*)(Ap + k0);
        *(float2*)&As2[acol+0][2*arow] = make_float2(a4.x, a4.x);
        *(float2*)&As2[acol+1][2*arow] = make_float2(a4.y, a4.y);
        *(float2*)&As2[acol+2][2*arow] = make_float2(a4.z, a4.z);
        *(float2*)&As2[acol+3][2*arow] = make_float2(a4.w, a4.w);
        *(float4*)&Bs[brow][bcol] = *(const float4*)(Bp + (long)k0*ldb);
        __syncthreads();
        #pragma unroll
        for (int kk = 0; kk < 8; kk++){
            unsigned long long ra2[8], rb2[4];
            #pragma unroll
            for (int i = 0; i < 8; i++)
                ra2[i] = *(const unsigned long long*)&As2[kk][ty*16 + 2*i];
            #pragma unroll
            for (int j = 0; j < 4; j++)
                rb2[j] = *(const unsigned long long*)&Bs[kk][tx*8 + 2*j];
            #pragma unroll
            for (int i = 0; i < 8; i++)
                #pragma unroll
                for (int j = 0; j < 4; j++)
                    acc[i][j] = fma2(ra2[i], rb2[j], acc[i][j]);
        }
        __syncthreads();
    }
    #pragma unroll
    for (int i = 0; i < 8; i++){
        long m = m0 + ty*8 + i;
        #pragma unroll
        for (int j = 0; j < 4; j++){
            int n = n0 + tx*8 + 2*j;
            float2 v = ull2f2(acc[i][j]);
            C[m*ldc + n]     = v.x + bias[n];
            C[m*ldc + n + 1] = v.y + bias[n + 1];
        }
    }
}

// ---------------------------------------------------------------------------
// Attention feature GEMM (f32x2) with on-the-fly 7H features, tanh+bias.
// ---------------------------------------------------------------------------
__global__ void __launch_bounds__(256) gemm_feats(
    const float* __restrict__ W1, const float* __restrict__ b1,
    const float* __restrict__ fact, const float* __restrict__ qvec,
    const float* __restrict__ mem, float* __restrict__ atth)
{
    __shared__ float As2[8][260];
    __shared__ float Bs[8][128];
    const int m0 = blockIdx.y*128, n0 = blockIdx.x*128;
    const int tid = threadIdx.x;
    const int tx = tid & 15, ty = tid >> 4;
    const int arow = tid >> 1, acol = (tid & 1)*4;
    const int brow = tid >> 5, bcol = (tid & 31)*4;
    const int m = m0 + arow, b = m >> 9;
    const float4* fp = (const float4*)(fact + (long)m*512);
    const float4* qp = (const float4*)(qvec + (long)b*512);
    const float4* mp = (const float4*)(mem  + (long)b*512);
    const float* Bp = W1 + (long)brow*512 + n0 + bcol;
    unsigned long long acc[8][4];
    #pragma unroll
    for (int i = 0; i < 8; i++)
        #pragma unroll
        for (int j = 0; j < 4; j++) acc[i][j] = 0ull;

    for (int k0 = 0; k0 < 3584; k0 += 8){
        int k = k0 + acol, seg = k >> 9, ki = (k & 511) >> 2;
        float4 v;
        if (seg == 0)      v = fp[ki];
        else if (seg == 1) v = mp[ki];
        else if (seg == 2) v = qp[ki];
        else if (seg == 3){ float4 f = fp[ki], q = qp[ki];
            v = make_float4(f.x*q.x, f.y*q.y, f.z*q.z, f.w*q.w); }
        else if (seg == 4){ float4 f = fp[ki], q = mp[ki];
            v = make_float4(f.x*q.x, f.y*q.y, f.z*q.z, f.w*q.w); }
        else if (seg == 5){ float4 f = fp[ki], q = qp[ki];
            v = make_float4(fabsf(f.x-q.x), fabsf(f.y-q.y), fabsf(f.z-q.z), fabsf(f.w-q.w)); }
        else              { float4 f = fp[ki], q = mp[ki];
            v = make_float4(fabsf(f.x-q.x), fabsf(f.y-q.y), fabsf(f.z-q.z), fabsf(f.w-q.w)); }
        *(float2*)&As2[acol+0][2*arow] = make_float2(v.x, v.x);
        *(float2*)&As2[acol+1][2*arow] = make_float2(v.y, v.y);
        *(float2*)&As2[acol+2][2*arow] = make_float2(v.z, v.z);
        *(float2*)&As2[acol+3][2*arow] = make_float2(v.w, v.w);
        *(float4*)&Bs[brow][bcol] = *(const float4*)(Bp + (long)k0*512);
        __syncthreads();
        #pragma unroll
        for (int kk = 0; kk < 8; kk++){
            unsigned long long ra2[8], rb2[4];
            #pragma unroll
            for (int i = 0; i < 8; i++)
                ra2[i] = *(const unsigned long long*)&As2[kk][ty*16 + 2*i];
            #pragma unroll
            for (int j = 0; j < 4; j++)
                rb2[j] = *(const unsigned long long*)&Bs[kk][tx*8 + 2*j];
            #pragma unroll
            for (int i = 0; i < 8; i++)
                #pragma unroll
                for (int j = 0; j < 4; j++)
                    acc[i][j] = fma2(ra2[i], rb2[j], acc[i][j]);
        }
        __syncthreads();
    }
    #pragma unroll
    for (int i = 0; i < 8; i++){
        long mm = m0 + ty*8 + i;
        #pragma unroll
        for (int j = 0; j < 4; j++){
            int n = n0 + tx*8 + 2*j;
            float2 v = ull2f2(acc[i][j]);
            atth[mm*512 + n]     = tanhf(v.x + b1[n]);
            atth[mm*512 + n + 1] = tanhf(v.y + b1[n + 1]);
        }
    }
}

__global__ void k_att2(const float* __restrict__ atth, const float* __restrict__ W2,
                       const float* __restrict__ b2, float* __restrict__ att){
    int m = blockIdx.x*8 + (threadIdx.x >> 5);
    int lane = threadIdx.x & 31;
    const float* row = atth + (long)m*512;
    float s = 0.f;
    #pragma unroll
    for (int i = 0; i < 16; i++) s = fmaf(row[lane + i*32], W2[lane + i*32], s);
    #pragma unroll
    for (int o = 16; o > 0; o >>= 1) s += __shfl_xor_sync(0xffffffffu, s, o);
    if (lane == 0) att[m] = s + b2[0];
}

__global__ void k_softmax(const float* __restrict__ att, float* __restrict__ gate){
    __shared__ float red[256];
    int b = blockIdx.x, tid = threadIdx.x;
    float v0 = att[b*512 + tid], v1 = att[b*512 + 256 + tid];
    red[tid] = fmaxf(v0, v1);
    __syncthreads();
    for (int s = 128; s > 0; s >>= 1){ if (tid < s) red[tid] = fmaxf(red[tid], red[tid+s]); __syncthreads(); }
    float mx = red[0];
    __syncthreads();
    float e0 = expf(v0 - mx), e1 = expf(v1 - mx);
    red[tid] = e0 + e1;
    __syncthreads();
    for (int s = 128; s > 0; s >>= 1){ if (tid < s) red[tid] += red[tid+s]; __syncthreads(); }
    float inv = 1.f/red[0];
    gate[b*512 + tid]       = e0*inv;
    gate[b*512 + 256 + tid] = e1*inv;
}

// ---------------------------------------------------------------------------
// Persistent question GRU: 32 blocks, 32 steps, 2 barriers/step.
// ---------------------------------------------------------------------------
__global__ void __launch_bounds__(256) pk_gru(
    const float* __restrict__ Wg,   // qWg + 512*1024 (h rows), ldb 1024
    const float* __restrict__ Wc,   // qWc + 512*512  (rh rows), ldb 512
    const float* __restrict__ preg, const float* __restrict__ prec,
    const int* __restrict__ qlen,
    float* __restrict__ h, float* __restrict__ rh, float* __restrict__ u)
{
    __shared__ float As[16][64];
    __shared__ float Bs[16][32];
    const int tid = threadIdx.x, bx = blockIdx.x;
    const int tx = tid & 31, ty = tid >> 5;
    const int arow = tid >> 2, acol = (tid & 3)*4;
    unsigned gen = 0;
    for (int t = 0; t < 32; t++){
        {   // gate phase: Z[64,1024] = h @ Wg_h, cols bx*32..
            const int n0 = bx*32;
            float acc[8] = {};
            for (int k0 = 0; k0 < 512; k0 += 16){
                float4 a4 = __ldcg((const float4*)(h + arow*512 + k0 + acol));
                As[acol+0][arow]=a4.x; As[acol+1][arow]=a4.y;
                As[acol+2][arow]=a4.z; As[acol+3][arow]=a4.w;
                if (tid < 128){
                    int kk = tid >> 3, c4 = (tid & 7)*4;
                    *(float4*)&Bs[kk][c4] = *(const float4*)(Wg + (long)(k0+kk)*1024 + n0 + c4);
                }
                __syncthreads();
                #pragma unroll
                for (int kk = 0; kk < 16; kk++){
                    float ra[8];
                    *(float4*)(ra)   = *(const float4*)&As[kk][ty*8];
                    *(float4*)(ra+4) = *(const float4*)&As[kk][ty*8+4];
                    float rb = Bs[kk][tx];
                    #pragma unroll
                    for (int i = 0; i < 8; i++) acc[i] = fmaf(ra[i], rb, acc[i]);
                }
                __syncthreads();
            }
            int n = n0 + tx;
            #pragma unroll
            for (int i = 0; i < 8; i++){
                int b = ty*8 + i;
                float z = acc[i] + preg[((long)b*32 + t)*1024 + n];
                float s = sigf(z);
                if (n < 512) __stcg(rh + b*512 + n, s * __ldcg(h + b*512 + n));
                else         __stcg(u + b*512 + (n - 512), s);
            }
        }
        flatbar(32, ++gen);
        if (bx < 16){   // candidate phase: Z[64,512] = rh @ Wc_h
            const int n0 = bx*32;
            float acc[8] = {};
            for (int k0 = 0; k0 < 512; k0 += 16){
                float4 a4 = __ldcg((const float4*)(rh + arow*512 + k0 + acol));
                As[acol+0][arow]=a4.x; As[acol+1][arow]=a4.y;
                As[acol+2][arow]=a4.z; As[acol+3][arow]=a4.w;
                if (tid < 128){
                    int kk = tid >> 3, c4 = (tid & 7)*4;
                    *(float4*)&Bs[kk][c4] = *(const float4*)(Wc + (long)(k0+kk)*512 + n0 + c4);
                }
                __syncthreads();
                #pragma unroll
                for (int kk = 0; kk < 16; kk++){
                    float ra[8];
                    *(float4*)(ra)   = *(const float4*)&As[kk][ty*8];
                    *(float4*)(ra+4) = *(const float4*)&As[kk][ty*8+4];
                    float rb = Bs[kk][tx];
                    #pragma unroll
                    for (int i = 0; i < 8; i++) acc[i] = fmaf(ra[i], rb, acc[i]);
                }
                __syncthreads();
            }
            int n = n0 + tx;
            #pragma unroll
            for (int i = 0; i < 8; i++){
                int b = ty*8 + i;
                float c = tanhf(acc[i] + prec[((long)b*32 + t)*512 + n]);
                float uu = __ldcg(u + b*512 + n);
                float ho = __ldcg(h + b*512 + n);
                float hn = (t < qlen[b]) ? (uu*ho + (1.f - uu)*c) : ho;
                __stcg(h + b*512 + n, hn);
            }
        }
        flatbar(32, ++gen);
    }
}

// ---------------------------------------------------------------------------
// Persistent bi-LSTM: 128 blocks (2 dirs x 64 hidden-chunks of 8), 512 steps,
// smem Z exchange for cross-gate epilogue, ping-pong h, 1 barrier/step.
// ---------------------------------------------------------------------------
__global__ void __launch_bounds__(256) pk_lstm(
    const float* __restrict__ Wfwh, const float* __restrict__ Wbwh, // + 512*2048
    const float* __restrict__ prefw, const float* __restrict__ prebw,
    const int* __restrict__ ilen,
    float* __restrict__ lh, float* __restrict__ lc,
    float* __restrict__ ffw, float* __restrict__ fbw)
{
    __shared__ float As[16][64];
    __shared__ float Bs[16][32];
    __shared__ float zs[64][32];
    const int tid = threadIdx.x;
    const int dir = blockIdx.x >> 6;
    const int hc8 = (blockIdx.x & 63)*8;
    const float* Wh  = dir ? Wbwh : Wfwh;
    const float* pre = dir ? prebw : prefw;
    float* cbuf = lc + dir*32768;
    float* outp = dir ? fbw : ffw;
    const int tx = tid & 31, ty = tid >> 5;
    const int arow = tid >> 2, acol = (tid & 3)*4;
    unsigned gen = 0;
    for (int t = 0; t < 512; t++){
        const int par = t & 1;
        const float* hin = lh + par*65536 + dir*32768;
        float* hout = lh + (par^1)*65536 + dir*32768;
        float acc[8] = {};
        for (int k0 = 0; k0 < 512; k0 += 16){
            float4 a4 = __ldcg((const float4*)(hin + arow*512 + k0 + acol));
            As[acol+0][arow]=a4.x; As[acol+1][arow]=a4.y;
            As[acol+2][arow]=a4.z; As[acol+3][arow]=a4.w;
            if (tid < 128){
                int kk = tid >> 3, rem = tid & 7;
                int gg = rem >> 1, h4 = (rem & 1)*4;
                *(float4*)&Bs[kk][gg*8 + h4] =
                    *(const float4*)(Wh + (long)(k0+kk)*2048 + gg*512 + hc8 + h4);
            }
            __syncthreads();
            #pragma unroll
            for (int kk = 0; kk < 16; kk++){
                float ra[8];
                *(float4*)(ra)   = *(const float4*)&As[kk][ty*8];
                *(float4*)(ra+4) = *(const float4*)&As[kk][ty*8+4];
                float rb = Bs[kk][tx];
                #pragma unroll
                for (int i = 0; i < 8; i++) acc[i] = fmaf(ra[i], rb, acc[i]);
            }
            __syncthreads();
        }
        #pragma unroll
        for (int i = 0; i < 8; i++) zs[ty*8 + i][tx] = acc[i];
        __syncthreads();
        #pragma unroll
        for (int e = 0; e < 2; e++){
            int uix = tid*2 + e;
            int b = uix >> 3, j = uix & 7, hc = hc8 + j;
            long prow = ((long)b*512 + t)*2048;
            float zi = zs[b][j]       + pre[prow + hc];
            float zj = zs[b][8 + j]   + pre[prow + 512 + hc];
            float zf = zs[b][16 + j]  + pre[prow + 1024 + hc];
            float zo = zs[b][24 + j]  + pre[prow + 1536 + hc];
            float c_old = cbuf[b*512 + hc];
            float cn = sigf(zf + 1.f)*c_old + sigf(zi)*tanhf(zj);
            float hn = sigf(zo)*tanhf(cn);
            int L = ilen[b];
            bool m = t < L;
            float h_old = __ldcg(hin + b*512 + hc);
            __stcg(hout + b*512 + hc, m ? hn : h_old);
            cbuf[b*512 + hc] = m ? cn : c_old;
            int wt = dir ? (m ? (L - 1 - t) : t) : t;
            __stcg(outp + ((long)b*512 + wt)*512 + hc, m ? hn : 0.f);
        }
        flatbar(128, ++gen);
    }
}

// ---------------------------------------------------------------------------
// Persistent AGRU: 64 blocks, each owns 8 output cols over full K.
// Per step: phase1 (z=h@Ur -> rh) BAR phase2 (z=rh@Uc -> h) BAR.
// A staged per 64-k chunk as duplicated f32x2 pairs; FFMA2 inner loop.
// ---------------------------------------------------------------------------
struct AgruSmem {
    float As2[64][130];   // dup pairs: As2[k][2b],[2b+1]
    float Us[64][8];      // U chunk [k][8 cols]
};

__device__ __forceinline__ unsigned long long agru_dot(
    const float* __restrict__ Asrc, const float* __restrict__ U,
    int n0, AgruSmem& sm)
{
    const int tid = threadIdx.x;
    const int cb = tid >> 2;            // batch row for compute
    const int cnp = tid & 3;            // col pair for compute
    const int sb = tid >> 2;            // batch row for A staging
    const int skq = (tid & 3) * 4;      // k sub-offset for A staging
    const int uk = tid >> 2;            // k row for U staging
    const int un = (tid & 3) * 2;       // col pair offset for U staging
    unsigned long long acc = 0ull;
    #pragma unroll 1
    for (int c = 0; c < 8; c++){
        const int kb = c*64;
        float4 pa[4];
        #pragma unroll
        for (int q = 0; q < 4; q++)
            pa[q] = __ldcg((const float4*)(Asrc + sb*512 + kb + skq + q*16));
        float2 pu = *(const float2*)(U + (long)(kb + uk)*512 + n0 + un);
        __syncthreads();    // previous chunk fully consumed
        #pragma unroll
        for (int q = 0; q < 4; q++){
            int k = skq + q*16;
            *(float2*)&sm.As2[k+0][2*sb] = make_float2(pa[q].x, pa[q].x);
            *(float2*)&sm.As2[k+1][2*sb] = make_float2(pa[q].y, pa[q].y);
            *(float2*)&sm.As2[k+2][2*sb] = make_float2(pa[q].z, pa[q].z);
            *(float2*)&sm.As2[k+3][2*sb] = make_float2(pa[q].w, pa[q].w);
        }
        *(float2*)&sm.Us[uk][un] = pu;
        __syncthreads();
        #pragma unroll 16
        for (int k = 0; k < 64; k++){
            unsigned long long a2 = *(const unsigned long long*)&sm.As2[k][2*cb];
            unsigned long long u2 = *(const unsigned long long*)&sm.Us[k][cnp*2];
            acc = fma2(a2, u2, acc);
        }
    }
    return acc;
}

__global__ void __launch_bounds__(256) pk_agru(
    const float* __restrict__ Ur, const float* __restrict__ Uc,
    const float* __restrict__ prer, const float* __restrict__ prec,
    const float* __restrict__ gate, const int* __restrict__ ilen,
    float* __restrict__ h, float* __restrict__ rh)
{
    __shared__ AgruSmem sm;
    const int tid = threadIdx.x;
    const int n0 = blockIdx.x*8;
    const int b = tid >> 2;
    const int n = n0 + (tid & 3)*2;
    unsigned gen = 0;
    for (int t = 0; t < 512; t++){
        // phase 1: r-gate -> rh
        {
            unsigned long long acc = agru_dot(h, Ur, n0, sm);
            float2 z = ull2f2(acc);
            long prow = ((long)b*512 + t)*512;
            float z0 = z.x + prer[prow + n];
            float z1 = z.y + prer[prow + n + 1];
            float h0 = __ldcg(h + b*512 + n);
            float h1 = __ldcg(h + b*512 + n + 1);
            __stcg(rh + b*512 + n,     sigf(z0)*h0);
            __stcg(rh + b*512 + n + 1, sigf(z1)*h1);
        }
        flatbar(64, ++gen);
        // phase 2: candidate -> h
        {
            unsigned long long acc = agru_dot(rh, Uc, n0, sm);
            float2 z = ull2f2(acc);
            long prow = ((long)b*512 + t)*512;
            float hh0 = tanhf(z.x + prec[prow + n]);
            float hh1 = tanhf(z.y + prec[prow + n + 1]);
            float g = gate[b*512 + t];
            bool m = t < ilen[b];
            float h0 = __ldcg(h + b*512 + n);
            float h1 = __ldcg(h + b*512 + n + 1);
            __stcg(h + b*512 + n,     m ? (g*hh0 + (1.f - g)*h0) : h0);
            __stcg(h + b*512 + n + 1, m ? (g*hh1 + (1.f - g)*h1) : h1);
        }
        flatbar(64, ++gen);
    }
}

// ---------------------------------------------------------------------------
// Concat-A GEMM: C[64,512] = act([p0|p1|p2|p3|p4] @ W + bias), segs 512 each.
// ---------------------------------------------------------------------------
template<int ACT>
__global__ void __launch_bounds__(256) k_catgemm(
    const float* __restrict__ p0, const float* __restrict__ p1,
    const float* __restrict__ p2, const float* __restrict__ p3,
    const float* __restrict__ p4,
    const float* __restrict__ W, const float* __restrict__ bias,
    float* __restrict__ C, int K)
{
    const float* segs[5] = {p0, p1, p2, p3, p4};
    __shared__ float As[16][64];
    __shared__ float Bs[16][64];
    const int n0 = blockIdx.x*64;
    const int tid = threadIdx.x;
    const int tx = tid & 31, ty = tid >> 5;
    const int arow = tid >> 2, acol = (tid & 3)*4;
    const int brow = tid >> 4, bcol = (tid & 15)*4;
    float acc[8][2] = {};
    for (int k0 = 0; k0 < K; k0 += 16){
        int k = k0 + acol;
        const float* sp = segs[k >> 9];
        float4 a4 = *(const float4*)(sp + arow*512 + (k & 511));
        As[acol+0][arow] = a4.x; As[acol+1][arow] = a4.y;
        As[acol+2][arow] = a4.z; As[acol+3][arow] = a4.w;
        *(float4*)&Bs[brow][bcol] = *(const float4*)(W + (long)(k0+brow)*512 + n0 + bcol);
        __syncthreads();
        #pragma unroll
        for (int kk = 0; kk < 16; kk++){
            float ra[8];
            *(float4*)(ra)   = *(const float4*)&As[kk][ty*8];
            *(float4*)(ra+4) = *(const float4*)&As[kk][ty*8+4];
            float2 rb = *(const float2*)&Bs[kk][tx*2];
            #pragma unroll
            for (int i = 0; i < 8; i++){
                acc[i][0] = fmaf(ra[i], rb.x, acc[i][0]);
                acc[i][1] = fmaf(ra[i], rb.y, acc[i][1]);
            }
        }
        __syncthreads();
    }
    #pragma unroll
    for (int i = 0; i < 8; i++){
        int b = ty*8 + i;
        #pragma unroll
        for (int j = 0; j < 2; j++){
            int n = n0 + tx*2 + j;
            float v = acc[i][j] + bias[n];
            if (ACT == 1) v = fmaxf(v, 0.f);
            C[b*512 + n] = v;
        }
    }
}

// ---------------------------------------------------------------------------
// host launcher
// ---------------------------------------------------------------------------
extern "C" void kernel_launch(void* const* d_in, const int* in_sizes, int n_in,
                              void* d_out, int out_size)
{
    (void)in_sizes; (void)n_in; (void)out_size;
    const int*   question  = (const int*)  d_in[0];
    const int*   input_ids = (const int*)  d_in[1];
    const int*   qlen      = (const int*)  d_in[2];
    const int*   ilen      = (const int*)  d_in[3];
    const int*   start     = (const int*)  d_in[4];
    const float* emb       = (const float*)d_in[5];
    const float* qWg       = (const float*)d_in[6];
    const float* qbg       = (const float*)d_in[7];
    const float* qWc       = (const float*)d_in[8];
    const float* qbc       = (const float*)d_in[9];
    const float* lfW       = (const float*)d_in[10];
    const float* lfb       = (const float*)d_in[11];
    const float* lbW       = (const float*)d_in[12];
    const float* lbb       = (const float*)d_in[13];
    const float* aW1       = (const float*)d_in[14];
    const float* ab1       = (const float*)d_in[15];
    const float* aW2       = (const float*)d_in[16];
    const float* ab2       = (const float*)d_in[17];
    const float* Wr        = (const float*)d_in[18];
    const float* Ur        = (const float*)d_in[19];
    const float* br        = (const float*)d_in[20];
    const float* Wc        = (const float*)d_in[21];
    const float* Uc        = (const float*)d_in[22];
    const float* bc        = (const float*)d_in[23];
    const float* hopW      = (const float*)d_in[24];
    const float* hopB      = (const float*)d_in[25];
    const float* osW       = (const float*)d_in[26];
    const float* osB       = (const float*)d_in[27];
    const float* oeW       = (const float*)d_in[28];
    const float* oeB       = (const float*)d_in[29];
    float* out = (float*)d_out;

    float* S = nullptr;
    cudaGetSymbolAddress((void**)&S, g_scratch);
    unsigned* flags = nullptr;
    cudaGetSymbolAddress((void**)&flags, g_flags);

    float* preqg = S + O_PREQG;
    float* preqc = S + O_PREQC;
    float* plfw  = S + O_PLFW;
    float* plbw  = S + O_PLBW;
    float* prer  = S + O_PRER;
    float* prec  = S + O_PREC;
    float* ffw   = S + O_FFW;
    float* fbw   = S + O_FBW;
    float* fact  = S + O_FACT;
    float* atth  = S + O_ATTH;
    float* att   = S + O_ATT;
    float* gate  = S + O_GATE;
    float* h     = S + O_H;
    float* rh    = S + O_RH;
    float* u     = S + O_U;
    float* qvec  = S + O_QVEC;
    float* lh    = S + O_LH;
    float* lc    = S + O_LC;
    float* mem   = S + O_MEM;
    float* as_   = S + O_AS;
    float* ae_   = S + O_AE;
    float* outs0 = S + O_OUTS0;
    float* oute0 = S + O_OUTE0;
    int*   rmfw  = (int*)(S + O_RMFW);
    int*   rmbw  = (int*)(S + O_RMBW);

    // launch 1-2: init + rowmaps (keeps ncu -s 5 capture on gemm128 plbw)
    k_init<<<512, 256>>>(S);
    k_rowmaps<<<128, 256>>>(input_ids, ilen, rmfw, rmbw);

    // launches 3-6: input-side precomputes (biases folded)
    gemm128<<<dim3(8, 16),  256>>>(emb, 512, question, qWg, 1024, qbg, preqg, 1024, 512);
    gemm128<<<dim3(4, 16),  256>>>(emb, 512, question, qWc,  512, qbc, preqc,  512, 512);
    gemm128<<<dim3(16,256), 256>>>(emb, 512, rmfw,     lfW, 2048, lfb, plfw,  2048, 512);
    gemm128<<<dim3(16,256), 256>>>(emb, 512, rmbw,     lbW, 2048, lbb, plbw,  2048, 512);

    // question GRU (persistent)
    k_zerou<<<1, 256>>>(flags);
    pk_gru<<<32, 256>>>(qWg + 512L*1024, qWc + 512L*512, preqg, preqc, qlen, h, rh, u);
    k_copy2<<<128, 256>>>(qvec, mem, h);

    // bi-LSTM (persistent)
    k_zerou<<<1, 256>>>(flags);
    pk_lstm<<<128, 256>>>(lfW + 512L*2048, lbW + 512L*2048, plfw, plbw, ilen, lh, lc, ffw, fbw);
    k_combine<<<16384, 256>>>(fact, ffw, fbw);

    // AGRU input-side precompute (hop-invariant)
    gemm128<<<dim3(4,256), 256>>>(fact, 512, nullptr, Wr, 512, br, prer, 512, 512);
    gemm128<<<dim3(4,256), 256>>>(fact, 512, nullptr, Wc, 512, bc, prec, 512, 512);

    // hops
    int cur = 0;
    for (int hop = 0; hop < 3; hop++){
        gemm_feats<<<dim3(4,256), 256>>>(aW1, ab1, fact, qvec, mem + cur*32768, atth);
        k_att2<<<4096, 256>>>(atth, aW2, ab2, att);
        k_softmax<<<64, 256>>>(att, gate);

        k_zero<<<128, 256>>>(h, 32768);
        k_zerou<<<1, 256>>>(flags);
        pk_agru<<<64, 256>>>(Ur, Uc, prer, prec, gate, ilen, h, rh);

        if (hop == 2){
            k_gather_rows<<<64, 256>>>(as_, emb, start);
            k_gather_rows<<<64, 256>>>(ae_, emb, start);
        }
        int nxt = cur ^ 1;
        k_catgemm<1><<<8, 256>>>(mem + cur*32768, h, qvec, as_, ae_,
                                 hopW + (long)hop*2560*512, hopB + hop*512,
                                 mem + nxt*32768, 2560);
        if (hop == 0){
            k_catgemm<0><<<8, 256>>>(mem + nxt*32768, qvec, qvec, qvec, qvec, osW, osB, outs0, 1024);
            k_catgemm<0><<<8, 256>>>(mem + nxt*32768, qvec, qvec, qvec, qvec, oeW, oeB, oute0, 1024);
            k_argmax_gather<<<64, 256>>>(outs0, emb, ae_);   // a_e = emb[argmax(output_s)]
            k_argmax_gather<<<64, 256>>>(oute0, emb, as_);   // a_s = emb[argmax(output_e)]
        }
        if (hop == 2){
            k_catgemm<0><<<8, 256>>>(mem + nxt*32768, qvec, qvec, qvec, qvec, osW, osB, out, 1024);
            k_catgemm<0><<<8, 256>>>(mem + nxt*32768, qvec, qvec, qvec, qvec, oeW, oeB, out + 32768, 1024);
        }
        cur = nxt;
    }
}